// round 1
// baseline (speedup 1.0000x reference)
#include <cuda_runtime.h>
#include <cuda_bf16.h>

// Problem constants (fixed by reference)
#define VOCAB        100000
#define EMB_DIM      128
#define HIDDEN       256
#define NUM_CLASSES  20
#define B_SIZE       4096
#define S_LEN        200

// Scratch for pooled vectors: 4096 * 128 floats = 2 MB (static device array; no allocs)
__device__ float g_pooled[B_SIZE * EMB_DIM];

// ---------------------------------------------------------------------------
// Kernel 1: embedding gather + masked mean pooling.
// One block (128 threads = 4 warps) per sequence.
// Warp w handles positions s = w, w+4, w+8, ...  Lane l handles dims [4l, 4l+4).
// 2-way unroll -> >=2 independent float4 gathers in flight per thread.
// ---------------------------------------------------------------------------
__global__ __launch_bounds__(128) void pool_kernel(
    const int* __restrict__ x,          // [B, S] token ids (int32)
    const int* __restrict__ seq_len,    // [B]
    const float* __restrict__ emb)      // [VOCAB, 128]
{
    const int b    = blockIdx.x;
    const int tid  = threadIdx.x;
    const int warp = tid >> 5;
    const int lane = tid & 31;

    const int L = seq_len[b];
    const int* xb = x + b * S_LEN;
    const float4* __restrict__ emb4 = reinterpret_cast<const float4*>(emb);

    float4 a0 = make_float4(0.f, 0.f, 0.f, 0.f);
    float4 a1 = make_float4(0.f, 0.f, 0.f, 0.f);

    int s = warp;
    // main loop: two positions per iteration (s, s+4) -> independent gathers
    for (; s + 4 < L; s += 8) {
        int t0 = xb[s];
        int t1 = xb[s + 4];
        float4 v0 = __ldg(&emb4[(size_t)t0 * 32 + lane]);
        float4 v1 = __ldg(&emb4[(size_t)t1 * 32 + lane]);
        a0.x += v0.x; a0.y += v0.y; a0.z += v0.z; a0.w += v0.w;
        a1.x += v1.x; a1.y += v1.y; a1.z += v1.z; a1.w += v1.w;
    }
    if (s < L) {
        int t0 = xb[s];
        float4 v0 = __ldg(&emb4[(size_t)t0 * 32 + lane]);
        a0.x += v0.x; a0.y += v0.y; a0.z += v0.z; a0.w += v0.w;
    }
    a0.x += a1.x; a0.y += a1.y; a0.z += a1.z; a0.w += a1.w;

    // cross-warp reduce (4 partial 128-dim vectors)
    __shared__ float4 red[4][32];
    red[warp][lane] = a0;
    __syncthreads();

    if (warp == 0) {
        float4 r0 = red[0][lane];
        float4 r1 = red[1][lane];
        float4 r2 = red[2][lane];
        float4 r3 = red[3][lane];
        float inv = 1.0f / (float)L;
        float4 out;
        out.x = (r0.x + r1.x + r2.x + r3.x) * inv;
        out.y = (r0.y + r1.y + r2.y + r3.y) * inv;
        out.z = (r0.z + r1.z + r2.z + r3.z) * inv;
        out.w = (r0.w + r1.w + r2.w + r3.w) * inv;
        reinterpret_cast<float4*>(g_pooled)[b * 32 + lane] = out;
    }
}

// ---------------------------------------------------------------------------
// Kernel 2: MLP.  hidden = relu(pooled @ W1 + b1); out = hidden @ W2 + b2
// 16 rows per block, 256 threads (one per hidden unit).
// ---------------------------------------------------------------------------
#define MLP_ROWS 16

__global__ __launch_bounds__(256) void mlp_kernel(
    const float* __restrict__ W1,   // [128, 256] row-major
    const float* __restrict__ b1,   // [256]
    const float* __restrict__ W2,   // [256, 20]  row-major
    const float* __restrict__ b2,   // [20]
    float* __restrict__ out)        // [B, 20]
{
    __shared__ float sp[MLP_ROWS][EMB_DIM];      // pooled tile  (8 KB)
    __shared__ float sh[MLP_ROWS][HIDDEN];       // hidden tile (16 KB)

    const int tid = threadIdx.x;
    const int rb  = blockIdx.x * MLP_ROWS;

    // load 16 pooled rows (float4, coalesced)
    {
        const float4* src = reinterpret_cast<const float4*>(g_pooled + rb * EMB_DIM);
        float4* dst = reinterpret_cast<float4*>(&sp[0][0]);
        for (int i = tid; i < MLP_ROWS * EMB_DIM / 4; i += 256)
            dst[i] = src[i];
    }
    __syncthreads();

    // hidden layer: thread tid owns column j = tid of W1
    const int j = tid;
    float h[MLP_ROWS];
    const float bj = b1[j];
    #pragma unroll
    for (int r = 0; r < MLP_ROWS; r++) h[r] = bj;

    #pragma unroll 4
    for (int k = 0; k < EMB_DIM; k += 4) {
        float w0 = W1[(k + 0) * HIDDEN + j];
        float w1 = W1[(k + 1) * HIDDEN + j];
        float w2 = W1[(k + 2) * HIDDEN + j];
        float w3 = W1[(k + 3) * HIDDEN + j];
        #pragma unroll
        for (int r = 0; r < MLP_ROWS; r++) {
            float4 p = *reinterpret_cast<const float4*>(&sp[r][k]);  // smem broadcast
            h[r] = fmaf(p.x, w0, h[r]);
            h[r] = fmaf(p.y, w1, h[r]);
            h[r] = fmaf(p.z, w2, h[r]);
            h[r] = fmaf(p.w, w3, h[r]);
        }
    }
    #pragma unroll
    for (int r = 0; r < MLP_ROWS; r++)
        sh[r][j] = fmaxf(h[r], 0.0f);
    __syncthreads();

    // output layer: 16 rows x 20 classes = 320 dots of length 256
    for (int o = tid; o < MLP_ROWS * NUM_CLASSES; o += 256) {
        int r = o / NUM_CLASSES;
        int c = o % NUM_CLASSES;
        float acc = b2[c];
        #pragma unroll 8
        for (int k = 0; k < HIDDEN; k++)
            acc = fmaf(sh[r][k], W2[k * NUM_CLASSES + c], acc);
        out[(rb + r) * NUM_CLASSES + c] = acc;
    }
}

// ---------------------------------------------------------------------------
// Inputs (metadata order): x[int32 B*S], seq_lengths[int32 B], emb[f32],
//                          W1[f32], b1[f32], W2[f32], b2[f32]
// Output: f32 [B, 20]
// ---------------------------------------------------------------------------
extern "C" void kernel_launch(void* const* d_in, const int* in_sizes, int n_in,
                              void* d_out, int out_size)
{
    const int*   x   = (const int*)  d_in[0];
    const int*   len = (const int*)  d_in[1];
    const float* emb = (const float*)d_in[2];
    const float* W1  = (const float*)d_in[3];
    const float* b1  = (const float*)d_in[4];
    const float* W2  = (const float*)d_in[5];
    const float* b2  = (const float*)d_in[6];
    float* out = (float*)d_out;

    pool_kernel<<<B_SIZE, 128>>>(x, len, emb);
    mlp_kernel<<<B_SIZE / MLP_ROWS, 256>>>(W1, b1, W2, b2, out);
}